// round 2
// baseline (speedup 1.0000x reference)
#include <cuda_runtime.h>

// gcnmask: N=50000 nodes, DEG=16 (edge_dst = repeat(arange(N),16) structural), F=128.
//
// Factored:
//   cproj = x @ Wm[0:128], nproj = x @ Wm[128:256]   (per node, 16x FLOP cut vs per-edge)
//   agg[n] = sum_e sigmoid(cproj[n]+nproj[src]) * x[src];  x_new = x + agg
//   support = x_new @ W;  out[n] = bias + sum_e adj[e]*support[src]
//
// All GEMMs: row-pair-packed fma.rn.f32x2 with k-transposed smem (ld.shared.v2.b64
// feeds two f32x2 operands directly, no pack movs). Sigmoid via MUFU.TANH.
// x and nproj interleaved in g_xn (float2) -> single LDG.64 gather stream in K2.

#define NN   50000
#define FF   128
#define DEG  16
#define R1   16    // rows/block k_proj  (50000/16 = 3125)
#define R2   16    // rows/block k2      (3125)
#define R3   8     // rows/block k3      (6250)
#define PAD  20    // smem row stride (floats): 16B-aligned, 4-way max conflict

typedef unsigned long long u64;

__device__ float  g_cproj[NN * FF];
__device__ float2 g_xn[NN * FF];       // {x, nproj} interleaved
__device__ float  g_support[NN * FF];

// ---- helpers ----
__device__ __forceinline__ u64 splat2(float v) {
    u64 r; asm("mov.b64 %0, {%1, %1};" : "=l"(r) : "f"(v)); return r;
}
__device__ __forceinline__ void fma2(u64& d, u64 a, u64 b) {
    asm("fma.rn.f32x2 %0, %1, %2, %0;" : "+l"(d) : "l"(a), "l"(b));
}
__device__ __forceinline__ void unpack2(u64 v, float& lo, float& hi) {
    asm("mov.b64 {%0, %1}, %2;" : "=f"(lo), "=f"(hi) : "l"(v));
}
__device__ __forceinline__ void lds128_2x64(u64& a, u64& b, unsigned addr) {
    asm volatile("ld.shared.v2.b64 {%0, %1}, [%2];" : "=l"(a), "=l"(b) : "r"(addr));
}
__device__ __forceinline__ unsigned smem_u32(const void* p) {
    unsigned r;
    asm("{ .reg .u64 t; cvta.to.shared.u64 t, %1; cvt.u32.u64 %0, t; }"
        : "=r"(r) : "l"(p));
    return r;
}
__device__ __forceinline__ float tanh_approx(float z) {
    float r; asm("tanh.approx.f32 %0, %1;" : "=f"(r) : "f"(z)); return r;
}

// ============================================================================
// K1: cproj/nproj GEMMs. Thread = output column j; rows packed in f32x2 pairs.
// ============================================================================
__global__ __launch_bounds__(128) void k_proj(const float* __restrict__ x,
                                              const float* __restrict__ wm) {
    __shared__ float xt[FF][PAD];   // xt[k][r] (transposed)
    const int j = threadIdx.x;
    const int row0 = blockIdx.x * R1;

#pragma unroll
    for (int r = 0; r < R1; ++r)
        xt[j][r] = x[(row0 + r) * FF + j];
    __syncthreads();

    u64 accc[R1 / 2], accn[R1 / 2];
#pragma unroll
    for (int q = 0; q < R1 / 2; ++q) { accc[q] = 0ull; accn[q] = 0ull; }

    const unsigned xt0 = smem_u32(&xt[0][0]);

#pragma unroll 4
    for (int k = 0; k < FF; ++k) {
        const u64 wc2 = splat2(wm[k * FF + j]);
        const u64 wn2 = splat2(wm[(FF + k) * FF + j]);
        const unsigned rowaddr = xt0 + k * (PAD * 4);
#pragma unroll
        for (int p = 0; p < R1 / 4; ++p) {     // LDS.128 -> rows 4p..4p+3
            u64 x01, x23;
            lds128_2x64(x01, x23, rowaddr + p * 16);
            fma2(accc[2 * p],     x01, wc2);
            fma2(accc[2 * p + 1], x23, wc2);
            fma2(accn[2 * p],     x01, wn2);
            fma2(accn[2 * p + 1], x23, wn2);
        }
    }

#pragma unroll
    for (int q = 0; q < R1 / 2; ++q) {
        float c0, c1, n0, n1;
        unpack2(accc[q], c0, c1);
        unpack2(accn[q], n0, n1);
        const int ra = row0 + 2 * q, rb = ra + 1;
        g_cproj[ra * FF + j] = c0;
        g_cproj[rb * FF + j] = c1;
        g_xn[ra * FF + j] = make_float2(x[ra * FF + j], n0);
        g_xn[rb * FF + j] = make_float2(x[rb * FF + j], n1);
    }
}

// ============================================================================
// K2: edge gather + tanh-sigmoid mask + agg -> x_new (transposed smem) ->
//     support = x_new @ W.
// ============================================================================
__global__ __launch_bounds__(128) void k_agg_support(const float* __restrict__ x,
                                                     const float* __restrict__ w,
                                                     const int* __restrict__ esrc) {
    __shared__ float xt[FF][PAD];
    const int j = threadIdx.x;
    const int base = blockIdx.x * R2;

#pragma unroll
    for (int r = 0; r < R2; ++r) {
        const int n = base + r;
        const float cp = g_cproj[n * FF + j];
        const int* es = esrc + n * DEG;
        float agg = 0.f;
#pragma unroll
        for (int e = 0; e < DEG; ++e) {
            const int s = es[e];                           // uniform broadcast
            const float2 xn = __ldg(&g_xn[s * FF + j]);    // L2 gather, LDG.64
            const float m = fmaf(0.5f, tanh_approx(0.5f * (cp + xn.y)), 0.5f);
            agg = fmaf(m, xn.x, agg);
        }
        xt[j][r] = x[n * FF + j] + agg;
    }
    __syncthreads();

    u64 acc[R2 / 2];
#pragma unroll
    for (int q = 0; q < R2 / 2; ++q) acc[q] = 0ull;

    const unsigned xt0 = smem_u32(&xt[0][0]);

#pragma unroll 4
    for (int k = 0; k < FF; ++k) {
        const u64 w2 = splat2(w[k * FF + j]);
        const unsigned rowaddr = xt0 + k * (PAD * 4);
#pragma unroll
        for (int p = 0; p < R2 / 4; ++p) {
            u64 x01, x23;
            lds128_2x64(x01, x23, rowaddr + p * 16);
            fma2(acc[2 * p],     x01, w2);
            fma2(acc[2 * p + 1], x23, w2);
        }
    }

#pragma unroll
    for (int q = 0; q < R2 / 2; ++q) {
        float s0, s1;
        unpack2(acc[q], s0, s1);
        g_support[(base + 2 * q)     * FF + j] = s0;
        g_support[(base + 2 * q + 1) * FF + j] = s1;
    }
}

// ============================================================================
// K3: out[n] = bias + sum_e adj[e]*support[src].  128 thr = 64 colpairs x 2 halves.
// ============================================================================
__global__ __launch_bounds__(128) void k_out(const float* __restrict__ adj,
                                             const int* __restrict__ esrc,
                                             const float* __restrict__ bias,
                                             float* __restrict__ out) {
    const int c2 = threadIdx.x & 63;       // column pair
    const int half = threadIdx.x >> 6;     // row half
    const int base = blockIdx.x * R3;
    const float2 b2 = *(const float2*)&bias[2 * c2];

#pragma unroll
    for (int rr = 0; rr < R3 / 2; ++rr) {
        const int n = base + half * (R3 / 2) + rr;
        const int* es = esrc + n * DEG;
        const float* av = adj + n * DEG;
        float2 acc = b2;
#pragma unroll
        for (int e = 0; e < DEG; ++e) {
            const int s = es[e];
            const float a = av[e];
            const float2 sv = __ldg((const float2*)&g_support[s * FF] + c2);
            acc.x = fmaf(a, sv.x, acc.x);
            acc.y = fmaf(a, sv.y, acc.y);
        }
        *(float2*)&out[n * FF + 2 * c2] = acc;
    }
}

// ============================================================================
extern "C" void kernel_launch(void* const* d_in, const int* in_sizes, int n_in,
                              void* d_out, int out_size) {
    const float* x    = (const float*)d_in[0];  // [N,128]
    const float* w    = (const float*)d_in[1];  // [128,128]
    const float* bias = (const float*)d_in[2];  // [128]
    const float* wm   = (const float*)d_in[3];  // [256,128]
    const float* adj  = (const float*)d_in[4];  // [E]
    const int*   esrc = (const int*)d_in[5];    // [E]
    float* out = (float*)d_out;

    k_proj<<<NN / R1, 128>>>(x, wm);
    k_agg_support<<<NN / R2, 128>>>(x, w, esrc);
    k_out<<<NN / R3, 128>>>(adj, esrc, bias, out);
}

// round 6
// speedup vs baseline: 1.0562x; 1.0562x over previous
#include <cuda_runtime.h>
#include <cuda_fp16.h>
#include <cstdint>

// gcnmask N=50000, DEG=16 (edge_dst = repeat(arange(N),16) structural), F=128.
// NOTE: harness compiles PTX at compute_103 (no 'a') -> tcgen05 unavailable.
// FFMA2 (fma.rn.f32x2) GEMMs, h-split threads; fp16 gather payloads (halve L2
// gather traffic); fp32 accumulation everywhere; sigmoid via MUFU.TANH.
//
//   cproj = x @ Wm[0:128], nproj = x @ Wm[128:256]
//   agg[n] = sum_e sigmoid(cproj[n]+nproj[src]) * x[src];  x_new = x + agg
//   support = x_new @ W;  out[n] = bias + sum_e adj[e]*support[src]

#define NN 50000
#define FF 128
#define DEG 16
#define R1 32          // rows/block k_proj; grid 1563 (guarded tail)
#define R2 32          // rows/block k2;     grid 1563
#define R3 16          // rows/block k3;     grid 3125 exact
#define G1 1563
#define PADR 36        // smem row stride (floats): 144B, 16B-aligned

typedef unsigned long long u64;

__device__ float   g_cproj[NN * FF];
__device__ __half2 g_xn2[NN * FF];     // {x, nproj} fp16 pair (4B) — gather stream K2
__device__ __half  g_sup[NN * FF];     // support fp16 — gather stream K3

// ---- helpers ----
__device__ __forceinline__ u64 splat2(float v) {
    u64 r; asm("mov.b64 %0, {%1, %1};" : "=l"(r) : "f"(v)); return r;
}
__device__ __forceinline__ void fma2(u64& d, u64 a, u64 b) {
    asm("fma.rn.f32x2 %0, %1, %2, %0;" : "+l"(d) : "l"(a), "l"(b));
}
__device__ __forceinline__ void unpack2(u64 v, float& lo, float& hi) {
    asm("mov.b64 {%0, %1}, %2;" : "=f"(lo), "=f"(hi) : "l"(v));
}
__device__ __forceinline__ void lds128_2x64(u64& a, u64& b, unsigned addr) {
    asm volatile("ld.shared.v2.b64 {%0, %1}, [%2];" : "=l"(a), "=l"(b) : "r"(addr));
}
__device__ __forceinline__ unsigned smem_u32(const void* p) {
    unsigned r;
    asm("{ .reg .u64 t; cvta.to.shared.u64 t, %1; cvt.u32.u64 %0, t; }" : "=r"(r) : "l"(p));
    return r;
}
__device__ __forceinline__ float tanh_approx(float z) {
    float r; asm("tanh.approx.f32 %0, %1;" : "=f"(r) : "f"(z)); return r;
}

// ============================================================================
// K1: cproj/nproj GEMMs. 256 threads = (col j, matrix h). 32 rows/block.
// Per k per thread: 1 LDG(w) + 1 splat + 8 LDS.v2.b64(broadcast) + 16 FFMA2.
// ============================================================================
__global__ __launch_bounds__(256) void k_proj(const float* __restrict__ x,
                                              const float* __restrict__ wm) {
    __shared__ __align__(16) float xt[FF][PADR];   // xt[k][r], 18KB
    const int tid = threadIdx.x;
    const int j = tid & 127, h = tid >> 7;
    const int row0 = blockIdx.x * R1;

#pragma unroll
    for (int i = 0; i < 16; ++i) {
        const int r = h * 16 + i, row = row0 + r;
        xt[j][r] = (row < NN) ? __ldg(&x[row * FF + j]) : 0.f;
    }
    __syncthreads();

    u64 acc[R1 / 2];
#pragma unroll
    for (int q = 0; q < R1 / 2; ++q) acc[q] = 0ull;

    const float* wp = wm + h * FF * FF + j;   // h=0: Wm_top, h=1: Wm_bot
    const unsigned xt0 = smem_u32(&xt[0][0]);

#pragma unroll 4
    for (int k = 0; k < FF; ++k) {
        const u64 w2 = splat2(__ldg(&wp[k * FF]));
        const unsigned rowaddr = xt0 + k * (PADR * 4);
#pragma unroll
        for (int p = 0; p < R1 / 4; ++p) {
            u64 a, b;
            lds128_2x64(a, b, rowaddr + p * 16);
            fma2(acc[2 * p],     a, w2);
            fma2(acc[2 * p + 1], b, w2);
        }
    }

#pragma unroll
    for (int q = 0; q < R1 / 2; ++q) {
        float v0, v1;
        unpack2(acc[q], v0, v1);
        const int ra = row0 + 2 * q, rb = ra + 1;
        if (h == 0) {                         // cproj fp32
            if (ra < NN) g_cproj[ra * FF + j] = v0;
            if (rb < NN) g_cproj[rb * FF + j] = v1;
        } else {                              // {x, nproj} fp16 pair
            if (ra < NN) g_xn2[ra * FF + j] = __floats2half2_rn(xt[j][2 * q], v0);
            if (rb < NN) g_xn2[rb * FF + j] = __floats2half2_rn(xt[j][2 * q + 1], v1);
        }
    }
}

// ============================================================================
// K2 (fused): half2 edge gather + tanh sigmoid + agg -> x_new (smem) ->
//             support = x_new @ W (h-split rows) -> g_sup fp16.
// ============================================================================
__global__ __launch_bounds__(256) void k_agg_support(const float* __restrict__ x,
                                                     const float* __restrict__ w,
                                                     const int* __restrict__ esrc) {
    __shared__ __align__(16) float xt[FF][PADR];
    const int tid = threadIdx.x;
    const int j = tid & 127, h = tid >> 7;
    const int base = blockIdx.x * R2;

#pragma unroll
    for (int i = 0; i < 16; ++i) {
        const int r = h * 16 + i, n = base + r;
        float v = 0.f;
        if (n < NN) {
            const float cp = g_cproj[n * FF + j];
            const int* es = esrc + n * DEG;
            float agg = 0.f;
#pragma unroll
            for (int e = 0; e < DEG; ++e) {
                const int s = es[e];                       // uniform broadcast
                const float2 f = __half22float2(g_xn2[s * FF + j]);  // 4B gather
                const float m = fmaf(0.5f, tanh_approx(0.5f * (cp + f.y)), 0.5f);
                agg = fmaf(m, f.x, agg);
            }
            v = __ldg(&x[n * FF + j]) + agg;
        }
        xt[j][r] = v;
    }
    __syncthreads();

    u64 acc[8];
#pragma unroll
    for (int q = 0; q < 8; ++q) acc[q] = 0ull;

    const float* wp = w + j;
    const unsigned xt0 = smem_u32(&xt[0][0]) + h * 64;   // h picks rows 16..31

#pragma unroll 4
    for (int k = 0; k < FF; ++k) {
        const u64 w2 = splat2(__ldg(&wp[k * FF]));
        const unsigned rowaddr = xt0 + k * (PADR * 4);
#pragma unroll
        for (int p = 0; p < 4; ++p) {
            u64 a, b;
            lds128_2x64(a, b, rowaddr + p * 16);
            fma2(acc[2 * p],     a, w2);
            fma2(acc[2 * p + 1], b, w2);
        }
    }

#pragma unroll
    for (int q = 0; q < 8; ++q) {
        float s0, s1;
        unpack2(acc[q], s0, s1);
        const int ra = base + h * 16 + 2 * q, rb = ra + 1;
        if (ra < NN) g_sup[ra * FF + j] = __float2half_rn(s0);
        if (rb < NN) g_sup[rb * FF + j] = __float2half_rn(s1);
    }
}

// ============================================================================
// K3: out[n] = bias + sum_e adj[e]*support[src]. half2 gather (256B/edge).
// 256 threads = (colpair cp, row-quarter rq); 16 rows/block.
// ============================================================================
__global__ __launch_bounds__(256) void k_out(const float* __restrict__ adj,
                                             const int* __restrict__ esrc,
                                             const float* __restrict__ bias,
                                             float* __restrict__ out) {
    const int tid = threadIdx.x;
    const int cp = tid & 63, rq = tid >> 6;
    const int base = blockIdx.x * R3;
    const float2 b2 = *(const float2*)&bias[2 * cp];

#pragma unroll
    for (int i = 0; i < R3 / 4; ++i) {
        const int n = base + rq * (R3 / 4) + i;
        const int* es = esrc + n * DEG;
        const float* av = adj + n * DEG;
        float2 acc = b2;
#pragma unroll
        for (int e = 0; e < DEG; ++e) {
            const int s = es[e];                 // uniform per quarter
            const float a = av[e];
            const float2 f =
                __half22float2(*(const __half2*)&g_sup[s * FF + 2 * cp]);
            acc.x = fmaf(a, f.x, acc.x);
            acc.y = fmaf(a, f.y, acc.y);
        }
        *(float2*)&out[n * FF + 2 * cp] = acc;
    }
}

// ============================================================================
extern "C" void kernel_launch(void* const* d_in, const int* in_sizes, int n_in,
                              void* d_out, int out_size) {
    const float* x    = (const float*)d_in[0];  // [N,128]
    const float* w    = (const float*)d_in[1];  // [128,128]
    const float* bias = (const float*)d_in[2];  // [128]
    const float* wm   = (const float*)d_in[3];  // [256,128]
    const float* adj  = (const float*)d_in[4];  // [E]
    const int*   esrc = (const int*)d_in[5];    // [E]
    float* out = (float*)d_out;

    k_proj<<<G1, 256>>>(x, wm);
    k_agg_support<<<G1, 256>>>(x, w, esrc);
    k_out<<<NN / R3, 256>>>(adj, esrc, bias, out);
}

// round 9
// speedup vs baseline: 1.2653x; 1.1979x over previous
#include <cuda_runtime.h>
#include <cuda_fp16.h>
#include <cstdint>

// gcnmask N=50000, DEG=16 (edge_dst = repeat(arange(N),16) structural), F=128.
// compute_103 PTX target: tcgen05 unavailable -> use sm_80-baseline
// mma.sync.m16n8k16 (fp16 in, fp32 acc) for both GEMMs. Gathers fp16 payloads,
// fp32 accumulation, sigmoid via MUFU.TANH.
//
//   cproj = x @ Wm[0:128], nproj = x @ Wm[128:256]
//   agg[n] = sum_e sigmoid(cproj[n]+nproj[src]) * x[src];  x_new = x + agg
//   support = x_new @ W;  out[n] = bias + sum_e adj[e]*support[src]

#define NN 50000
#define FF 128
#define DEG 16
#define NT 391          // ceil(50000/128) row tiles
#define STR 136         // smem row stride in halfs (272B): conflict-free frag loads
#define SMEMSZ (2 * 128 * STR * 2)   // A tile + B tile, fp16
#define R3 16

__device__ float   g_cproj[NN * FF];
__device__ __half2 g_xn2[NN * FF];     // {x, nproj} fp16 pair — K2 gather stream
__device__ __half  g_sup[NN * FF];     // support fp16 — K3 gather stream

// ---- helpers ----
__device__ __forceinline__ float tanh_approx(float z) {
    float r; asm("tanh.approx.f32 %0, %1;" : "=f"(r) : "f"(z)); return r;
}
__device__ __forceinline__ uint32_t lds32(const __half* p) {
    return *(const uint32_t*)p;
}
__device__ __forceinline__ void mma16816(float& d0, float& d1, float& d2, float& d3,
                                         uint32_t a0, uint32_t a1, uint32_t a2, uint32_t a3,
                                         uint32_t b0, uint32_t b1) {
    asm volatile(
        "mma.sync.aligned.m16n8k16.row.col.f32.f16.f16.f32 "
        "{%0,%1,%2,%3}, {%4,%5,%6,%7}, {%8,%9}, {%0,%1,%2,%3};"
        : "+f"(d0), "+f"(d1), "+f"(d2), "+f"(d3)
        : "r"(a0), "r"(a1), "r"(a2), "r"(a3), "r"(b0), "r"(b1));
}

// Warp-tile GEMM over K=128: warp (wr 0..3, wc 0..1), tile 32(M) x 64(N).
// As[r][k], Bs[n][k] both k-contiguous, stride STR halfs.
// Fragment maps (m16n8k16): g=lane>>2, t=lane&3:
//   a0=A[m+g][kk+2t] a1=A[m+g+8][kk+2t] a2=A[m+g][kk+2t+8] a3=A[m+g+8][kk+2t+8]
//   b0=Bt[n+g][kk+2t] b1=Bt[n+g][kk+2t+8]
//   c0=C[m+g][n+2t] c1=C[m+g][n+2t+1] c2=C[m+g+8][n+2t] c3=C[m+g+8][n+2t+1]
#define GEMM_BODY(AS, BS, ACC, MB, NB, G, T)                                   \
    _Pragma("unroll")                                                          \
    for (int ks = 0; ks < 8; ++ks) {                                           \
        const int kk = ks * 16;                                                \
        uint32_t af[2][4];                                                     \
        _Pragma("unroll")                                                      \
        for (int mt = 0; mt < 2; ++mt) {                                       \
            const __half* ap = (AS) + ((MB) + mt * 16 + (G)) * STR + kk + 2 * (T); \
            af[mt][0] = lds32(ap);                                             \
            af[mt][1] = lds32(ap + 8 * STR);                                   \
            af[mt][2] = lds32(ap + 8);                                         \
            af[mt][3] = lds32(ap + 8 * STR + 8);                               \
        }                                                                      \
        _Pragma("unroll")                                                      \
        for (int nt = 0; nt < 8; ++nt) {                                       \
            const __half* bp = (BS) + ((NB) + nt * 8 + (G)) * STR + kk + 2 * (T); \
            const uint32_t b0 = lds32(bp), b1 = lds32(bp + 8);                 \
            _Pragma("unroll")                                                  \
            for (int mt = 0; mt < 2; ++mt)                                     \
                mma16816(ACC[mt][nt][0], ACC[mt][nt][1], ACC[mt][nt][2],       \
                         ACC[mt][nt][3], af[mt][0], af[mt][1], af[mt][2],      \
                         af[mt][3], b0, b1);                                   \
        }                                                                      \
    }

// ============================================================================
// K1: C = x_tile @ Wm_half.  grid (391, 2); h=0 -> cproj, h=1 -> g_xn2.
// ============================================================================
__global__ __launch_bounds__(256, 2) void k_proj_mma(const float* __restrict__ x,
                                                     const float* __restrict__ wm) {
    extern __shared__ __half sm[];
    __half* As = sm;                 // [128][STR]
    __half* Bs = sm + 128 * STR;     // [128][STR] = Wm_half transposed [n][k]
    const int tid = threadIdx.x;
    const int h = blockIdx.y;
    const int row0 = blockIdx.x * 128;

    // Fill A (x rows, fp32->fp16) and B (Wm[h*128+k][n] -> Bs[n][k])
#pragma unroll 8
    for (int i = 0; i < 64; ++i) {
        const int idx = i * 256 + tid;
        const int r = idx >> 7, c = idx & 127;
        const int row = row0 + r;
        As[r * STR + c] = __float2half_rn(row < NN ? __ldg(&x[row * FF + c]) : 0.f);
        const int k = r, n = c;
        Bs[n * STR + k] = __float2half_rn(__ldg(&wm[(h * FF + k) * FF + n]));
    }
    __syncthreads();

    const int warp = tid >> 5, lane = tid & 31;
    const int wr = warp >> 1, wc = warp & 1;
    const int mb = wr * 32, nb = wc * 64;
    const int g = lane >> 2, t = lane & 3;

    float acc[2][8][4];
#pragma unroll
    for (int mt = 0; mt < 2; ++mt)
#pragma unroll
        for (int nt = 0; nt < 8; ++nt)
#pragma unroll
            for (int q = 0; q < 4; ++q) acc[mt][nt][q] = 0.f;

    GEMM_BODY(As, Bs, acc, mb, nb, g, t)

    // Epilogue
#pragma unroll
    for (int mt = 0; mt < 2; ++mt) {
        const int rA = row0 + mb + mt * 16 + g;      // rows rA and rA+8
#pragma unroll
        for (int nt = 0; nt < 8; ++nt) {
            const int col = nb + nt * 8 + 2 * t;
            if (h == 0) {
                if (rA < NN)
                    *(float2*)&g_cproj[rA * FF + col] =
                        make_float2(acc[mt][nt][0], acc[mt][nt][1]);
                if (rA + 8 < NN)
                    *(float2*)&g_cproj[(rA + 8) * FF + col] =
                        make_float2(acc[mt][nt][2], acc[mt][nt][3]);
            } else {
                if (rA < NN) {
                    const float2 xv = *(const float2*)&x[rA * FF + col];
                    g_xn2[rA * FF + col]     = __floats2half2_rn(xv.x, acc[mt][nt][0]);
                    g_xn2[rA * FF + col + 1] = __floats2half2_rn(xv.y, acc[mt][nt][1]);
                }
                if (rA + 8 < NN) {
                    const float2 xv = *(const float2*)&x[(rA + 8) * FF + col];
                    g_xn2[(rA + 8) * FF + col]     = __floats2half2_rn(xv.x, acc[mt][nt][2]);
                    g_xn2[(rA + 8) * FF + col + 1] = __floats2half2_rn(xv.y, acc[mt][nt][3]);
                }
            }
        }
    }
}

// ============================================================================
// K2: gather (edge mask + agg -> x_new, fp16 into As) then support = x_new @ W.
// ============================================================================
__global__ __launch_bounds__(256, 2) void k_agg_support(const float* __restrict__ x,
                                                        const float* __restrict__ w,
                                                        const int* __restrict__ esrc) {
    extern __shared__ __half sm[];
    __half* As = sm;
    __half* Bs = sm + 128 * STR;
    const int tid = threadIdx.x;
    const int row0 = blockIdx.x * 128;

    // B = W transposed
#pragma unroll 8
    for (int i = 0; i < 64; ++i) {
        const int idx = i * 256 + tid;
        const int k = idx >> 7, n = idx & 127;
        Bs[n * STR + k] = __float2half_rn(__ldg(&w[k * FF + n]));
    }

    // Gather phase: rows row0..row0+127, cols j (128 per half-block)
    const int j = tid & 127, rh = tid >> 7;
#pragma unroll 2
    for (int i = 0; i < 64; ++i) {
        const int r = rh * 64 + i;
        const int n = row0 + r;
        float v = 0.f;
        if (n < NN) {
            const float cp = __ldg(&g_cproj[n * FF + j]);
            const int* es = esrc + n * DEG;
            float agg = 0.f;
#pragma unroll
            for (int e = 0; e < DEG; ++e) {
                const int s = es[e];                            // uniform per warp
                const float2 f = __half22float2(g_xn2[s * FF + j]);
                const float m = fmaf(0.5f, tanh_approx(0.5f * (cp + f.y)), 0.5f);
                agg = fmaf(m, f.x, agg);
            }
            v = __ldg(&x[n * FF + j]) + agg;
        }
        As[r * STR + j] = __float2half_rn(v);
    }
    __syncthreads();

    const int warp = tid >> 5, lane = tid & 31;
    const int wr = warp >> 1, wc = warp & 1;
    const int mb = wr * 32, nb = wc * 64;
    const int g = lane >> 2, t = lane & 3;

    float acc[2][8][4];
#pragma unroll
    for (int mt = 0; mt < 2; ++mt)
#pragma unroll
        for (int nt = 0; nt < 8; ++nt)
#pragma unroll
            for (int q = 0; q < 4; ++q) acc[mt][nt][q] = 0.f;

    GEMM_BODY(As, Bs, acc, mb, nb, g, t)

#pragma unroll
    for (int mt = 0; mt < 2; ++mt) {
        const int rA = row0 + mb + mt * 16 + g;
#pragma unroll
        for (int nt = 0; nt < 8; ++nt) {
            const int col = nb + nt * 8 + 2 * t;
            if (rA < NN)
                *(__half2*)&g_sup[rA * FF + col] =
                    __floats2half2_rn(acc[mt][nt][0], acc[mt][nt][1]);
            if (rA + 8 < NN)
                *(__half2*)&g_sup[(rA + 8) * FF + col] =
                    __floats2half2_rn(acc[mt][nt][2], acc[mt][nt][3]);
        }
    }
}

// ============================================================================
// K3: out[n] = bias + sum_e adj[e]*support[src].  (unchanged from R6)
// ============================================================================
__global__ __launch_bounds__(256) void k_out(const float* __restrict__ adj,
                                             const int* __restrict__ esrc,
                                             const float* __restrict__ bias,
                                             float* __restrict__ out) {
    const int tid = threadIdx.x;
    const int cp = tid & 63, rq = tid >> 6;
    const int base = blockIdx.x * R3;
    const float2 b2 = *(const float2*)&bias[2 * cp];

#pragma unroll
    for (int i = 0; i < R3 / 4; ++i) {
        const int n = base + rq * (R3 / 4) + i;
        const int* es = esrc + n * DEG;
        const float* av = adj + n * DEG;
        float2 acc = b2;
#pragma unroll
        for (int e = 0; e < DEG; ++e) {
            const int s = es[e];
            const float a = av[e];
            const float2 f = __half22float2(*(const __half2*)&g_sup[s * FF + 2 * cp]);
            acc.x = fmaf(a, f.x, acc.x);
            acc.y = fmaf(a, f.y, acc.y);
        }
        *(float2*)&out[n * FF + 2 * cp] = acc;
    }
}

// ============================================================================
extern "C" void kernel_launch(void* const* d_in, const int* in_sizes, int n_in,
                              void* d_out, int out_size) {
    const float* x    = (const float*)d_in[0];  // [N,128]
    const float* w    = (const float*)d_in[1];  // [128,128]
    const float* bias = (const float*)d_in[2];  // [128]
    const float* wm   = (const float*)d_in[3];  // [256,128]
    const float* adj  = (const float*)d_in[4];  // [E]
    const int*   esrc = (const int*)d_in[5];    // [E]
    float* out = (float*)d_out;

    cudaFuncSetAttribute(k_proj_mma, cudaFuncAttributeMaxDynamicSharedMemorySize, SMEMSZ);
    cudaFuncSetAttribute(k_agg_support, cudaFuncAttributeMaxDynamicSharedMemorySize, SMEMSZ);

    k_proj_mma<<<dim3(NT, 2), 256, SMEMSZ>>>(x, wm);
    k_agg_support<<<NT, 256, SMEMSZ>>>(x, w, esrc);
    k_out<<<NN / R3, 256>>>(adj, esrc, bias, out);
}

// round 11
// speedup vs baseline: 1.4088x; 1.1134x over previous
#include <cuda_runtime.h>
#include <cuda_fp16.h>
#include <cstdint>

// gcnmask N=50000, DEG=16 (edge_dst = repeat(arange(N),16) structural), F=128.
// compute_103 PTX target: tcgen05 unavailable -> sm_80-baseline mma.sync.m16n8k16
// (fp16 in, fp32 acc). ldmatrix fragment loads. Weights pre-transposed to fp16
// once (k_prep). Gathers fp16 payloads, fp32 accumulation, MUFU.TANH sigmoid.
// (Resubmission of R10 — previous run died to a container-infra failure, no data.)
//
//   cproj = x @ Wm[0:128], nproj = x @ Wm[128:256]
//   agg[n] = sum_e sigmoid(cproj[n]+nproj[src]) * x[src];  x_new = x + agg
//   support = x_new @ W;  out[n] = bias + sum_e adj[e]*support[src]

#define NN 50000
#define FF 128
#define DEG 16
#define NT 391            // ceil(50000/128)
#define STR 136           // smem/B row stride in halfs (272B) -> conflict-free frags
#define MATH (128 * STR)  // halfs per weight tile
#define SM1 ((128 + 256) * STR * 2)   // k_proj: A + both Wm halves
#define SM2 ((128 + 128) * STR * 2)   // k2:     A + W
#define R3 16

__device__ float   g_cproj[NN * FF];
__device__ __half2 g_xn2[NN * FF];     // {x, nproj} fp16 pair — K2 gather stream
__device__ __half  g_sup[NN * FF];     // support fp16 — K3 gather stream
__device__ __align__(16) __half g_B[3 * MATH];  // WmTop^T, WmBot^T, W^T  [n][k]

// ---- helpers ----
__device__ __forceinline__ float tanh_approx(float z) {
    float r; asm("tanh.approx.f32 %0, %1;" : "=f"(r) : "f"(z)); return r;
}
__device__ __forceinline__ unsigned smem_u32(const void* p) {
    unsigned r;
    asm("{ .reg .u64 t; cvta.to.shared.u64 t, %1; cvt.u32.u64 %0, t; }" : "=r"(r) : "l"(p));
    return r;
}
__device__ __forceinline__ void ldmat4(uint32_t& r0, uint32_t& r1, uint32_t& r2,
                                       uint32_t& r3, unsigned addr) {
    asm volatile("ldmatrix.sync.aligned.m8n8.x4.shared.b16 {%0,%1,%2,%3}, [%4];"
                 : "=r"(r0), "=r"(r1), "=r"(r2), "=r"(r3) : "r"(addr));
}
__device__ __forceinline__ void mma16816(float& d0, float& d1, float& d2, float& d3,
                                         uint32_t a0, uint32_t a1, uint32_t a2, uint32_t a3,
                                         uint32_t b0, uint32_t b1) {
    asm volatile(
        "mma.sync.aligned.m16n8k16.row.col.f32.f16.f16.f32 "
        "{%0,%1,%2,%3}, {%4,%5,%6,%7}, {%8,%9}, {%0,%1,%2,%3};"
        : "+f"(d0), "+f"(d1), "+f"(d2), "+f"(d3)
        : "r"(a0), "r"(a1), "r"(a2), "r"(a3), "r"(b0), "r"(b1));
}

// Warp tile 32(M) x 64(N), K=128. As[r][k], Bs[n][k], k-contiguous stride STR.
// aaddr[mt]: lane base for ldmatrix.x4 of A (rows mb+mt*16+(lane&15), col (lane>>4)*8)
// baddr[p] : lane base for B pair p (nt=2p,2p+1)
// acc[mt][nt][4]: c0=C[m+g][n+2t] c1=+1 c2=row+8 c3=row+8,+1
#define GEMM_BODY(AADDR, BADDR, ACC)                                           \
    _Pragma("unroll")                                                          \
    for (int ks = 0; ks < 8; ++ks) {                                           \
        const int kb = ks * 32;                                                \
        uint32_t af[2][4];                                                     \
        ldmat4(af[0][0], af[0][1], af[0][2], af[0][3], (AADDR)[0] + kb);       \
        ldmat4(af[1][0], af[1][1], af[1][2], af[1][3], (AADDR)[1] + kb);       \
        _Pragma("unroll")                                                      \
        for (int p = 0; p < 4; ++p) {                                          \
            uint32_t b00, b01, b10, b11;                                       \
            ldmat4(b00, b01, b10, b11, (BADDR)[p] + kb);                       \
            _Pragma("unroll")                                                  \
            for (int mt = 0; mt < 2; ++mt) {                                   \
                mma16816(ACC[mt][2 * p][0], ACC[mt][2 * p][1],                 \
                         ACC[mt][2 * p][2], ACC[mt][2 * p][3],                 \
                         af[mt][0], af[mt][1], af[mt][2], af[mt][3], b00, b01);\
                mma16816(ACC[mt][2 * p + 1][0], ACC[mt][2 * p + 1][1],         \
                         ACC[mt][2 * p + 1][2], ACC[mt][2 * p + 1][3],         \
                         af[mt][0], af[mt][1], af[mt][2], af[mt][3], b10, b11);\
            }                                                                  \
        }                                                                      \
    }

// ============================================================================
// K0: one-time weight transpose to fp16 [n][k] stride-STR tiles.
// ============================================================================
__global__ __launch_bounds__(256) void k_prep(const float* __restrict__ w,
                                              const float* __restrict__ wm) {
    const int idx = blockIdx.x * 256 + threadIdx.x;   // 192 blocks = 49152
    const int m = idx >> 14, r = idx & 16383;
    const int k = r >> 7, n = r & 127;
    float v;
    if (m == 0)      v = __ldg(&wm[k * FF + n]);
    else if (m == 1) v = __ldg(&wm[(FF + k) * FF + n]);
    else             v = __ldg(&w[k * FF + n]);
    g_B[m * MATH + n * STR + k] = __float2half_rn(v);
}

// ============================================================================
// K1: both Wm halves resident; A tile (x, fp16) built once; GEMM run for h=0
// (-> cproj fp32) and h=1 (-> g_xn2 {x,nproj} fp16).
// ============================================================================
__global__ __launch_bounds__(256, 2) void k_proj_mma(const float* __restrict__ x) {
    extern __shared__ __half sm[];
    __half* As = sm;                 // [128][STR]
    __half* Bs = sm + 128 * STR;     // [256][STR]: h=0 rows 0-127, h=1 rows 128-255
    const int tid = threadIdx.x;
    const int row0 = blockIdx.x * 128;

    {   // B: vectorized copy of both prepped Wm tiles (4352 uint4)
        uint4* dst = (uint4*)Bs;
        const uint4* src = (const uint4*)g_B;
#pragma unroll
        for (int i = 0; i < 17; ++i) dst[i * 256 + tid] = src[i * 256 + tid];
    }
    {   // A: float4 x -> 2x half2 -> uint2 store (4096 items)
#pragma unroll
        for (int i = 0; i < 16; ++i) {
            const int idx = i * 256 + tid;
            const int r = idx >> 5, c4 = (idx & 31) * 4;
            const int row = row0 + r;
            float4 v = make_float4(0.f, 0.f, 0.f, 0.f);
            if (row < NN) v = *(const float4*)&x[row * FF + c4];
            __half2 lo = __floats2half2_rn(v.x, v.y);
            __half2 hi = __floats2half2_rn(v.z, v.w);
            *(uint2*)&As[r * STR + c4] =
                make_uint2(*(uint32_t*)&lo, *(uint32_t*)&hi);
        }
    }
    __syncthreads();

    const int warp = tid >> 5, lane = tid & 31;
    const int wr = warp >> 1, wc = warp & 1;
    const int mb = wr * 32, nb = wc * 64;
    const int g = lane >> 2, t = lane & 3, q = lane >> 3;

    const unsigned As32 = smem_u32(As);
    const unsigned Bs32 = smem_u32(Bs);
    unsigned aaddr[2], baddr[4];
#pragma unroll
    for (int mt = 0; mt < 2; ++mt)
        aaddr[mt] = As32 + ((mb + mt * 16 + (lane & 15)) * STR + (lane >> 4) * 8) * 2;
    const int brow_l = (lane & 7) + (q >> 1) * 8;
    const int bcol_l = (q & 1) * 8;

    float acc[2][8][4];
#pragma unroll
    for (int h = 0; h < 2; ++h) {
#pragma unroll
        for (int p = 0; p < 4; ++p)
            baddr[p] = Bs32 + ((h * 128 + nb + p * 16 + brow_l) * STR + bcol_l) * 2;
#pragma unroll
        for (int mt = 0; mt < 2; ++mt)
#pragma unroll
            for (int nt = 0; nt < 8; ++nt)
#pragma unroll
                for (int c = 0; c < 4; ++c) acc[mt][nt][c] = 0.f;

        GEMM_BODY(aaddr, baddr, acc)

#pragma unroll
        for (int mt = 0; mt < 2; ++mt) {
            const int rl = mb + mt * 16 + g;          // local rows rl, rl+8
            const int rA = row0 + rl;
#pragma unroll
            for (int nt = 0; nt < 8; ++nt) {
                const int col = nb + nt * 8 + 2 * t;
                if (h == 0) {
                    if (rA < NN)
                        *(float2*)&g_cproj[rA * FF + col] =
                            make_float2(acc[mt][nt][0], acc[mt][nt][1]);
                    if (rA + 8 < NN)
                        *(float2*)&g_cproj[(rA + 8) * FF + col] =
                            make_float2(acc[mt][nt][2], acc[mt][nt][3]);
                } else {
                    if (rA < NN) {
                        __half2 v0; v0.x = As[rl * STR + col];
                        v0.y = __float2half_rn(acc[mt][nt][0]);
                        __half2 v1; v1.x = As[rl * STR + col + 1];
                        v1.y = __float2half_rn(acc[mt][nt][1]);
                        g_xn2[rA * FF + col] = v0;
                        g_xn2[rA * FF + col + 1] = v1;
                    }
                    if (rA + 8 < NN) {
                        __half2 v2; v2.x = As[(rl + 8) * STR + col];
                        v2.y = __float2half_rn(acc[mt][nt][2]);
                        __half2 v3; v3.x = As[(rl + 8) * STR + col + 1];
                        v3.y = __float2half_rn(acc[mt][nt][3]);
                        g_xn2[(rA + 8) * FF + col] = v2;
                        g_xn2[(rA + 8) * FF + col + 1] = v3;
                    }
                }
            }
        }
    }
}

// ============================================================================
// K2: edge gather (mask + agg -> x_new fp16 into As) then support = x_new @ W.
// ============================================================================
__global__ __launch_bounds__(256, 2) void k_agg_support(const float* __restrict__ x,
                                                        const int* __restrict__ esrc) {
    extern __shared__ __half sm[];
    __half* As = sm;
    __half* Bs = sm + 128 * STR;
    const int tid = threadIdx.x;
    const int row0 = blockIdx.x * 128;

    {   // B: prepped W^T tile (2176 uint4)
        uint4* dst = (uint4*)Bs;
        const uint4* src = (const uint4*)(g_B + 2 * MATH);
#pragma unroll
        for (int i = 0; i < 9; ++i) {
            const int idx = i * 256 + tid;
            if (idx < 2176) dst[idx] = src[idx];
        }
    }

    // Gather: 2 half-blocks x 64 rows; thread handles col j of row r
    const int j = tid & 127, rh = tid >> 7;
#pragma unroll 2
    for (int i = 0; i < 64; ++i) {
        const int r = rh * 64 + i;
        const int n = row0 + r;
        float v = 0.f;
        if (n < NN) {
            const float cp = __ldg(&g_cproj[n * FF + j]);
            const int* es = esrc + n * DEG;
            float agg = 0.f;
#pragma unroll
            for (int e = 0; e < DEG; ++e) {
                const int s = es[e];                         // uniform per warp
                const float2 f = __half22float2(g_xn2[s * FF + j]);
                const float m = fmaf(0.5f, tanh_approx(0.5f * (cp + f.y)), 0.5f);
                agg = fmaf(m, f.x, agg);
            }
            v = __ldg(&x[n * FF + j]) + agg;
        }
        As[r * STR + j] = __float2half_rn(v);
    }
    __syncthreads();

    const int warp = tid >> 5, lane = tid & 31;
    const int wr = warp >> 1, wc = warp & 1;
    const int mb = wr * 32, nb = wc * 64;
    const int g = lane >> 2, t = lane & 3, q = lane >> 3;

    const unsigned As32 = smem_u32(As);
    const unsigned Bs32 = smem_u32(Bs);
    unsigned aaddr[2], baddr[4];
#pragma unroll
    for (int mt = 0; mt < 2; ++mt)
        aaddr[mt] = As32 + ((mb + mt * 16 + (lane & 15)) * STR + (lane >> 4) * 8) * 2;
#pragma unroll
    for (int p = 0; p < 4; ++p)
        baddr[p] = Bs32 +
                   ((nb + p * 16 + (lane & 7) + (q >> 1) * 8) * STR + (q & 1) * 8) * 2;

    float acc[2][8][4];
#pragma unroll
    for (int mt = 0; mt < 2; ++mt)
#pragma unroll
        for (int nt = 0; nt < 8; ++nt)
#pragma unroll
            for (int c = 0; c < 4; ++c) acc[mt][nt][c] = 0.f;

    GEMM_BODY(aaddr, baddr, acc)

#pragma unroll
    for (int mt = 0; mt < 2; ++mt) {
        const int rA = row0 + mb + mt * 16 + g;
#pragma unroll
        for (int nt = 0; nt < 8; ++nt) {
            const int col = nb + nt * 8 + 2 * t;
            if (rA < NN)
                *(__half2*)&g_sup[rA * FF + col] =
                    __floats2half2_rn(acc[mt][nt][0], acc[mt][nt][1]);
            if (rA + 8 < NN)
                *(__half2*)&g_sup[(rA + 8) * FF + col] =
                    __floats2half2_rn(acc[mt][nt][2], acc[mt][nt][3]);
        }
    }
}

// ============================================================================
// K3: out[n] = bias + sum_e adj[e]*support[src].
// ============================================================================
__global__ __launch_bounds__(256) void k_out(const float* __restrict__ adj,
                                             const int* __restrict__ esrc,
                                             const float* __restrict__ bias,
                                             float* __restrict__ out) {
    const int tid = threadIdx.x;
    const int cp = tid & 63, rq = tid >> 6;
    const int base = blockIdx.x * R3;
    const float2 b2 = *(const float2*)&bias[2 * cp];

#pragma unroll
    for (int i = 0; i < R3 / 4; ++i) {
        const int n = base + rq * (R3 / 4) + i;
        const int* es = esrc + n * DEG;
        const float* av = adj + n * DEG;
        float2 acc = b2;
#pragma unroll
        for (int e = 0; e < DEG; ++e) {
            const int s = es[e];
            const float a = av[e];
            const float2 f = __half22float2(*(const __half2*)&g_sup[s * FF + 2 * cp]);
            acc.x = fmaf(a, f.x, acc.x);
            acc.y = fmaf(a, f.y, acc.y);
        }
        *(float2*)&out[n * FF + 2 * cp] = acc;
    }
}

// ============================================================================
extern "C" void kernel_launch(void* const* d_in, const int* in_sizes, int n_in,
                              void* d_out, int out_size) {
    const float* x    = (const float*)d_in[0];  // [N,128]
    const float* w    = (const float*)d_in[1];  // [128,128]
    const float* bias = (const float*)d_in[2];  // [128]
    const float* wm   = (const float*)d_in[3];  // [256,128]
    const float* adj  = (const float*)d_in[4];  // [E]
    const int*   esrc = (const int*)d_in[5];    // [E]
    float* out = (float*)d_out;

    cudaFuncSetAttribute(k_proj_mma, cudaFuncAttributeMaxDynamicSharedMemorySize, SM1);
    cudaFuncSetAttribute(k_agg_support, cudaFuncAttributeMaxDynamicSharedMemorySize, SM2);

    k_prep<<<192, 256>>>(w, wm);
    k_proj_mma<<<NT, 256, SM1>>>(x);
    k_agg_support<<<NT, 256, SM2>>>(x, esrc);
    k_out<<<NN / R3, 256>>>(adj, esrc, bias, out);
}

// round 12
// speedup vs baseline: 2.2752x; 1.6150x over previous
#include <cuda_runtime.h>
#include <cuda_fp16.h>
#include <cstdint>

// gcnmask N=50000, DEG=16 (edge_dst = repeat(arange(N),16) structural), F=128.
// compute_103 PTX target: tcgen05 unavailable -> sm_80-baseline mma.sync.m16n8k16
// (fp16 in, fp32 acc), ldmatrix fragments, weights pre-transposed fp16 (k_prep).
// R12: 512-thread CTAs (32 warps/SM) + uint2 col-pair gather to hide L2 latency.
//
//   cproj = x @ Wm[0:128], nproj = x @ Wm[128:256]
//   agg[n] = sum_e sigmoid(cproj[n]+nproj[src]) * x[src];  x_new = x + agg
//   support = x_new @ W;  out[n] = bias + sum_e adj[e]*support[src]

#define NN 50000
#define FF 128
#define DEG 16
#define NT 391            // ceil(50000/128)
#define STR 136           // smem row stride in halfs (272B) -> conflict-free frags
#define MATH (128 * STR)  // halfs per weight tile
#define SM1 ((128 + 256) * STR * 2)   // k_proj: A + both Wm halves
#define SM2 ((128 + 128) * STR * 2)   // k2:     A + W
#define R3 16

__device__ float   g_cproj[NN * FF];
__device__ __align__(16) __half2 g_xn2[NN * FF];  // {x, nproj} — K2 gather stream
__device__ __align__(16) __half  g_sup[NN * FF];  // support fp16 — K3 gather stream
__device__ __align__(16) __half  g_B[3 * MATH];   // WmTop^T, WmBot^T, W^T  [n][k]

// ---- helpers ----
__device__ __forceinline__ float tanh_approx(float z) {
    float r; asm("tanh.approx.f32 %0, %1;" : "=f"(r) : "f"(z)); return r;
}
__device__ __forceinline__ unsigned smem_u32(const void* p) {
    unsigned r;
    asm("{ .reg .u64 t; cvta.to.shared.u64 t, %1; cvt.u32.u64 %0, t; }" : "=r"(r) : "l"(p));
    return r;
}
__device__ __forceinline__ void ldmat4(uint32_t& r0, uint32_t& r1, uint32_t& r2,
                                       uint32_t& r3, unsigned addr) {
    asm volatile("ldmatrix.sync.aligned.m8n8.x4.shared.b16 {%0,%1,%2,%3}, [%4];"
                 : "=r"(r0), "=r"(r1), "=r"(r2), "=r"(r3) : "r"(addr));
}
__device__ __forceinline__ void mma16816(float& d0, float& d1, float& d2, float& d3,
                                         uint32_t a0, uint32_t a1, uint32_t a2, uint32_t a3,
                                         uint32_t b0, uint32_t b1) {
    asm volatile(
        "mma.sync.aligned.m16n8k16.row.col.f32.f16.f16.f32 "
        "{%0,%1,%2,%3}, {%4,%5,%6,%7}, {%8,%9}, {%0,%1,%2,%3};"
        : "+f"(d0), "+f"(d1), "+f"(d2), "+f"(d3)
        : "r"(a0), "r"(a1), "r"(a2), "r"(a3), "r"(b0), "r"(b1));
}

// 16 warps, warp tile 32(M) x 32(N), K=128. As[r][k], Bs[n][k], stride STR.
// aaddr[mt]: ldmatrix.x4 A base (rows mb+mt*16+(lane&15), col (lane>>4)*8)
// baddr[p]:  ldmatrix.x4 B base (rows nb+p*16+..., p=0,1 -> nt pairs (2p,2p+1))
// acc[mt][nt][4]: c0=C[m+g][n+2t] c1=+1 c2=row+8 c3=row+8,+1
#define GEMM_BODY(AADDR, BADDR, ACC)                                           \
    _Pragma("unroll")                                                          \
    for (int ks = 0; ks < 8; ++ks) {                                           \
        const int kb = ks * 32;                                                \
        uint32_t af[2][4];                                                     \
        ldmat4(af[0][0], af[0][1], af[0][2], af[0][3], (AADDR)[0] + kb);       \
        ldmat4(af[1][0], af[1][1], af[1][2], af[1][3], (AADDR)[1] + kb);       \
        _Pragma("unroll")                                                      \
        for (int p = 0; p < 2; ++p) {                                          \
            uint32_t b00, b01, b10, b11;                                       \
            ldmat4(b00, b01, b10, b11, (BADDR)[p] + kb);                       \
            _Pragma("unroll")                                                  \
            for (int mt = 0; mt < 2; ++mt) {                                   \
                mma16816(ACC[mt][2 * p][0], ACC[mt][2 * p][1],                 \
                         ACC[mt][2 * p][2], ACC[mt][2 * p][3],                 \
                         af[mt][0], af[mt][1], af[mt][2], af[mt][3], b00, b01);\
                mma16816(ACC[mt][2 * p + 1][0], ACC[mt][2 * p + 1][1],         \
                         ACC[mt][2 * p + 1][2], ACC[mt][2 * p + 1][3],         \
                         af[mt][0], af[mt][1], af[mt][2], af[mt][3], b10, b11);\
            }                                                                  \
        }                                                                      \
    }

// ============================================================================
// K0: one-time weight transpose to fp16 [n][k] stride-STR tiles.
// ============================================================================
__global__ __launch_bounds__(256) void k_prep(const float* __restrict__ w,
                                              const float* __restrict__ wm) {
    const int idx = blockIdx.x * 256 + threadIdx.x;   // 192 blocks = 49152
    const int m = idx >> 14, r = idx & 16383;
    const int k = r >> 7, n = r & 127;
    float v;
    if (m == 0)      v = __ldg(&wm[k * FF + n]);
    else if (m == 1) v = __ldg(&wm[(FF + k) * FF + n]);
    else             v = __ldg(&w[k * FF + n]);
    g_B[m * MATH + n * STR + k] = __float2half_rn(v);
}

// ============================================================================
// K1: both Wm halves resident; A tile built once; GEMM h=0 -> cproj fp32,
// h=1 -> g_xn2 {x,nproj} fp16 (uint2 coalesced stores).
// ============================================================================
__global__ __launch_bounds__(512, 2) void k_proj_mma(const float* __restrict__ x) {
    extern __shared__ __half sm[];
    __half* As = sm;                 // [128][STR]
    __half* Bs = sm + 128 * STR;     // [256][STR]: h=0 rows 0-127, h=1 rows 128-255
    const int tid = threadIdx.x;
    const int row0 = blockIdx.x * 128;

    {   // B: both prepped Wm tiles (4352 uint4)
        uint4* dst = (uint4*)Bs;
        const uint4* src = (const uint4*)g_B;
#pragma unroll
        for (int i = 0; i < 9; ++i) {
            const int idx = i * 512 + tid;
            if (idx < 4352) dst[idx] = src[idx];
        }
    }
    {   // A: float4 x -> 2x half2 -> uint2 store (4096 items)
#pragma unroll
        for (int i = 0; i < 8; ++i) {
            const int idx = i * 512 + tid;
            const int r = idx >> 5, c4 = (idx & 31) * 4;
            const int row = row0 + r;
            float4 v = make_float4(0.f, 0.f, 0.f, 0.f);
            if (row < NN) v = *(const float4*)&x[row * FF + c4];
            __half2 lo = __floats2half2_rn(v.x, v.y);
            __half2 hi = __floats2half2_rn(v.z, v.w);
            *(uint2*)&As[r * STR + c4] = make_uint2(*(uint32_t*)&lo, *(uint32_t*)&hi);
        }
    }
    __syncthreads();

    const int warp = tid >> 5, lane = tid & 31;
    const int wr = warp >> 2, wc = warp & 3;
    const int mb = wr * 32, nb = wc * 32;
    const int g = lane >> 2, t = lane & 3, q = lane >> 3;

    const unsigned As32 = smem_u32(As);
    const unsigned Bs32 = smem_u32(Bs);
    unsigned aaddr[2], baddr[2];
#pragma unroll
    for (int mt = 0; mt < 2; ++mt)
        aaddr[mt] = As32 + ((mb + mt * 16 + (lane & 15)) * STR + (lane >> 4) * 8) * 2;
    const int brow_l = (lane & 7) + (q >> 1) * 8;
    const int bcol_l = (q & 1) * 8;

    float acc[2][4][4];
#pragma unroll
    for (int h = 0; h < 2; ++h) {
#pragma unroll
        for (int p = 0; p < 2; ++p)
            baddr[p] = Bs32 + ((h * 128 + nb + p * 16 + brow_l) * STR + bcol_l) * 2;
#pragma unroll
        for (int mt = 0; mt < 2; ++mt)
#pragma unroll
            for (int nt = 0; nt < 4; ++nt)
#pragma unroll
                for (int c = 0; c < 4; ++c) acc[mt][nt][c] = 0.f;

        GEMM_BODY(aaddr, baddr, acc)

#pragma unroll
        for (int mt = 0; mt < 2; ++mt) {
            const int rl = mb + mt * 16 + g;          // local rows rl, rl+8
            const int rA = row0 + rl;
#pragma unroll
            for (int nt = 0; nt < 4; ++nt) {
                const int col = nb + nt * 8 + 2 * t;
                if (h == 0) {
                    if (rA < NN)
                        *(float2*)&g_cproj[rA * FF + col] =
                            make_float2(acc[mt][nt][0], acc[mt][nt][1]);
                    if (rA + 8 < NN)
                        *(float2*)&g_cproj[(rA + 8) * FF + col] =
                            make_float2(acc[mt][nt][2], acc[mt][nt][3]);
                } else {
                    if (rA < NN) {
                        const uint32_t xa = *(uint32_t*)&As[rl * STR + col];
                        __half2 v0, v1;
                        v0.x = ((const __half2*)&xa)->x;
                        v0.y = __float2half_rn(acc[mt][nt][0]);
                        v1.x = ((const __half2*)&xa)->y;
                        v1.y = __float2half_rn(acc[mt][nt][1]);
                        *(uint2*)&g_xn2[rA * FF + col] =
                            make_uint2(*(uint32_t*)&v0, *(uint32_t*)&v1);
                    }
                    if (rA + 8 < NN) {
                        const uint32_t xa = *(uint32_t*)&As[(rl + 8) * STR + col];
                        __half2 v2, v3;
                        v2.x = ((const __half2*)&xa)->x;
                        v2.y = __float2half_rn(acc[mt][nt][2]);
                        v3.x = ((const __half2*)&xa)->y;
                        v3.y = __float2half_rn(acc[mt][nt][3]);
                        *(uint2*)&g_xn2[(rA + 8) * FF + col] =
                            make_uint2(*(uint32_t*)&v2, *(uint32_t*)&v3);
                    }
                }
            }
        }
    }
}

// ============================================================================
// K2: edge gather (col-pair uint2 loads, mask + agg -> x_new fp16 into As)
// then support = x_new @ W.  512 threads.
// ============================================================================
__global__ __launch_bounds__(512, 2) void k_agg_support(const float* __restrict__ x,
                                                        const int* __restrict__ esrc) {
    extern __shared__ __half sm[];
    __half* As = sm;
    __half* Bs = sm + 128 * STR;
    const int tid = threadIdx.x;
    const int row0 = blockIdx.x * 128;

    {   // B: prepped W^T tile (2176 uint4)
        uint4* dst = (uint4*)Bs;
        const uint4* src = (const uint4*)(g_B + 2 * MATH);
#pragma unroll
        for (int i = 0; i < 5; ++i) {
            const int idx = i * 512 + tid;
            if (idx < 2176) dst[idx] = src[idx];
        }
    }

    // Gather: thread = (colpair c2, row-group rg); 16 rows per thread.
    const int c2 = tid & 63, rg = tid >> 6;
#pragma unroll 2
    for (int i = 0; i < 16; ++i) {
        const int r = rg * 16 + i;
        const int n = row0 + r;
        float2 v = make_float2(0.f, 0.f);
        if (n < NN) {
            const float2 cp2 = *(const float2*)&g_cproj[n * FF + 2 * c2];
            const int* es = esrc + n * DEG;
            float a0 = 0.f, a1 = 0.f;
#pragma unroll
            for (int e = 0; e < DEG; ++e) {
                const int s = es[e];                            // uniform per warp
                const uint2 u = *(const uint2*)&g_xn2[s * FF + 2 * c2];  // 8B gather
                const float2 f0 = __half22float2(*(const __half2*)&u.x);
                const float2 f1 = __half22float2(*(const __half2*)&u.y);
                a0 = fmaf(fmaf(0.5f, tanh_approx(0.5f * (cp2.x + f0.y)), 0.5f), f0.x, a0);
                a1 = fmaf(fmaf(0.5f, tanh_approx(0.5f * (cp2.y + f1.y)), 0.5f), f1.x, a1);
            }
            const float2 xv = *(const float2*)&x[n * FF + 2 * c2];
            v.x = xv.x + a0;
            v.y = xv.y + a1;
        }
        const __half2 hv = __floats2half2_rn(v.x, v.y);
        *(uint32_t*)&As[r * STR + 2 * c2] = *(const uint32_t*)&hv;
    }
    __syncthreads();

    const int warp = tid >> 5, lane = tid & 31;
    const int wr = warp >> 2, wc = warp & 3;
    const int mb = wr * 32, nb = wc * 32;
    const int g = lane >> 2, t = lane & 3, q = lane >> 3;

    const unsigned As32 = smem_u32(As);
    const unsigned Bs32 = smem_u32(Bs);
    unsigned aaddr[2], baddr[2];
#pragma unroll
    for (int mt = 0; mt < 2; ++mt)
        aaddr[mt] = As32 + ((mb + mt * 16 + (lane & 15)) * STR + (lane >> 4) * 8) * 2;
#pragma unroll
    for (int p = 0; p < 2; ++p)
        baddr[p] = Bs32 +
                   ((nb + p * 16 + (lane & 7) + (q >> 1) * 8) * STR + (q & 1) * 8) * 2;

    float acc[2][4][4];
#pragma unroll
    for (int mt = 0; mt < 2; ++mt)
#pragma unroll
        for (int nt = 0; nt < 4; ++nt)
#pragma unroll
            for (int c = 0; c < 4; ++c) acc[mt][nt][c] = 0.f;

    GEMM_BODY(aaddr, baddr, acc)

#pragma unroll
    for (int mt = 0; mt < 2; ++mt) {
        const int rA = row0 + mb + mt * 16 + g;
#pragma unroll
        for (int nt = 0; nt < 4; ++nt) {
            const int col = nb + nt * 8 + 2 * t;
            if (rA < NN)
                *(__half2*)&g_sup[rA * FF + col] =
                    __floats2half2_rn(acc[mt][nt][0], acc[mt][nt][1]);
            if (rA + 8 < NN)
                *(__half2*)&g_sup[(rA + 8) * FF + col] =
                    __floats2half2_rn(acc[mt][nt][2], acc[mt][nt][3]);
        }
    }
}

// ============================================================================
// K3: out[n] = bias + sum_e adj[e]*support[src].  (~L2 floor; unchanged)
// ============================================================================
__global__ __launch_bounds__(256) void k_out(const float* __restrict__ adj,
                                             const int* __restrict__ esrc,
                                             const float* __restrict__ bias,
                                             float* __restrict__ out) {
    const int tid = threadIdx.x;
    const int cp = tid & 63, rq = tid >> 6;
    const int base = blockIdx.x * R3;
    const float2 b2 = *(const float2*)&bias[2 * cp];

#pragma unroll
    for (int i = 0; i < R3 / 4; ++i) {
        const int n = base + rq * (R3 / 4) + i;
        const int* es = esrc + n * DEG;
        const float* av = adj + n * DEG;
        float2 acc = b2;
#pragma unroll
        for (int e = 0; e < DEG; ++e) {
            const int s = es[e];
            const float a = av[e];
            const float2 f = __half22float2(*(const __half2*)&g_sup[s * FF + 2 * cp]);
            acc.x = fmaf(a, f.x, acc.x);
            acc.y = fmaf(a, f.y, acc.y);
        }
        *(float2*)&out[n * FF + 2 * cp] = acc;
    }
}

// ============================================================================
extern "C" void kernel_launch(void* const* d_in, const int* in_sizes, int n_in,
                              void* d_out, int out_size) {
    const float* x    = (const float*)d_in[0];  // [N,128]
    const float* w    = (const float*)d_in[1];  // [128,128]
    const float* bias = (const float*)d_in[2];  // [128]
    const float* wm   = (const float*)d_in[3];  // [256,128]
    const float* adj  = (const float*)d_in[4];  // [E]
    const int*   esrc = (const int*)d_in[5];    // [E]
    float* out = (float*)d_out;

    cudaFuncSetAttribute(k_proj_mma, cudaFuncAttributeMaxDynamicSharedMemorySize, SM1);
    cudaFuncSetAttribute(k_agg_support, cudaFuncAttributeMaxDynamicSharedMemorySize, SM2);

    k_prep<<<192, 256>>>(w, wm);
    k_proj_mma<<<NT, 512, SM1>>>(x);
    k_agg_support<<<NT, 512, SM2>>>(x, esrc);
    k_out<<<NN / R3, 256>>>(adj, esrc, bias, out);
}

// round 13
// speedup vs baseline: 2.7825x; 1.2230x over previous
#include <cuda_runtime.h>
#include <cuda_fp16.h>
#include <cstdint>

// gcnmask N=50000, DEG=16 (edge_dst = repeat(arange(N),16) structural), F=128.
// compute_103 PTX target: tcgen05 unavailable -> sm_80-baseline mma.sync.m16n8k16
// (fp16 in, fp32 acc), ldmatrix fragments, weights pre-transposed fp16 (k_prep).
// R13: uint4 (16B) gathers in K2 and K3 — gather loops are LSU-instruction-bound,
// wide loads cut warp load instructions 2-4x at identical sector traffic.
//
//   cproj = x @ Wm[0:128], nproj = x @ Wm[128:256]
//   agg[n] = sum_e sigmoid(cproj[n]+nproj[src]) * x[src];  x_new = x + agg
//   support = x_new @ W;  out[n] = bias + sum_e adj[e]*support[src]

#define NN 50000
#define FF 128
#define DEG 16
#define NT 391            // ceil(50000/128)
#define STR 136           // smem row stride in halfs (272B) -> conflict-free frags
#define MATH (128 * STR)  // halfs per weight tile
#define SM1 ((128 + 256) * STR * 2)   // k_proj: A + both Wm halves
#define SM2 ((128 + 128) * STR * 2)   // k2:     A + W
#define R3 16

__device__ float   g_cproj[NN * FF];
__device__ __align__(16) __half2 g_xn2[NN * FF];  // {x, nproj} — K2 gather stream
__device__ __align__(16) __half  g_sup[NN * FF];  // support fp16 — K3 gather stream
__device__ __align__(16) __half  g_B[3 * MATH];   // WmTop^T, WmBot^T, W^T  [n][k]

// ---- helpers ----
__device__ __forceinline__ float tanh_approx(float z) {
    float r; asm("tanh.approx.f32 %0, %1;" : "=f"(r) : "f"(z)); return r;
}
__device__ __forceinline__ unsigned smem_u32(const void* p) {
    unsigned r;
    asm("{ .reg .u64 t; cvta.to.shared.u64 t, %1; cvt.u32.u64 %0, t; }" : "=r"(r) : "l"(p));
    return r;
}
__device__ __forceinline__ void ldmat4(uint32_t& r0, uint32_t& r1, uint32_t& r2,
                                       uint32_t& r3, unsigned addr) {
    asm volatile("ldmatrix.sync.aligned.m8n8.x4.shared.b16 {%0,%1,%2,%3}, [%4];"
                 : "=r"(r0), "=r"(r1), "=r"(r2), "=r"(r3) : "r"(addr));
}
__device__ __forceinline__ void mma16816(float& d0, float& d1, float& d2, float& d3,
                                         uint32_t a0, uint32_t a1, uint32_t a2, uint32_t a3,
                                         uint32_t b0, uint32_t b1) {
    asm volatile(
        "mma.sync.aligned.m16n8k16.row.col.f32.f16.f16.f32 "
        "{%0,%1,%2,%3}, {%4,%5,%6,%7}, {%8,%9}, {%0,%1,%2,%3};"
        : "+f"(d0), "+f"(d1), "+f"(d2), "+f"(d3)
        : "r"(a0), "r"(a1), "r"(a2), "r"(a3), "r"(b0), "r"(b1));
}

// 16 warps, warp tile 32(M) x 32(N), K=128. As[r][k], Bs[n][k], stride STR.
#define GEMM_BODY(AADDR, BADDR, ACC)                                           \
    _Pragma("unroll")                                                          \
    for (int ks = 0; ks < 8; ++ks) {                                           \
        const int kb = ks * 32;                                                \
        uint32_t af[2][4];                                                     \
        ldmat4(af[0][0], af[0][1], af[0][2], af[0][3], (AADDR)[0] + kb);       \
        ldmat4(af[1][0], af[1][1], af[1][2], af[1][3], (AADDR)[1] + kb);       \
        _Pragma("unroll")                                                      \
        for (int p = 0; p < 2; ++p) {                                          \
            uint32_t b00, b01, b10, b11;                                       \
            ldmat4(b00, b01, b10, b11, (BADDR)[p] + kb);                       \
            _Pragma("unroll")                                                  \
            for (int mt = 0; mt < 2; ++mt) {                                   \
                mma16816(ACC[mt][2 * p][0], ACC[mt][2 * p][1],                 \
                         ACC[mt][2 * p][2], ACC[mt][2 * p][3],                 \
                         af[mt][0], af[mt][1], af[mt][2], af[mt][3], b00, b01);\
                mma16816(ACC[mt][2 * p + 1][0], ACC[mt][2 * p + 1][1],         \
                         ACC[mt][2 * p + 1][2], ACC[mt][2 * p + 1][3],         \
                         af[mt][0], af[mt][1], af[mt][2], af[mt][3], b10, b11);\
            }                                                                  \
        }                                                                      \
    }

// ============================================================================
// K0: one-time weight transpose to fp16 [n][k] stride-STR tiles.
// ============================================================================
__global__ __launch_bounds__(256) void k_prep(const float* __restrict__ w,
                                              const float* __restrict__ wm) {
    const int idx = blockIdx.x * 256 + threadIdx.x;   // 192 blocks = 49152
    const int m = idx >> 14, r = idx & 16383;
    const int k = r >> 7, n = r & 127;
    float v;
    if (m == 0)      v = __ldg(&wm[k * FF + n]);
    else if (m == 1) v = __ldg(&wm[(FF + k) * FF + n]);
    else             v = __ldg(&w[k * FF + n]);
    g_B[m * MATH + n * STR + k] = __float2half_rn(v);
}

// ============================================================================
// K1: both Wm halves resident; A tile built once; GEMM h=0 -> cproj fp32,
// h=1 -> g_xn2 {x,nproj} fp16 (uint2 coalesced stores).  (unchanged from R12)
// ============================================================================
__global__ __launch_bounds__(512, 2) void k_proj_mma(const float* __restrict__ x) {
    extern __shared__ __half sm[];
    __half* As = sm;                 // [128][STR]
    __half* Bs = sm + 128 * STR;     // [256][STR]
    const int tid = threadIdx.x;
    const int row0 = blockIdx.x * 128;

    {   // B: both prepped Wm tiles (4352 uint4)
        uint4* dst = (uint4*)Bs;
        const uint4* src = (const uint4*)g_B;
#pragma unroll
        for (int i = 0; i < 9; ++i) {
            const int idx = i * 512 + tid;
            if (idx < 4352) dst[idx] = src[idx];
        }
    }
    {   // A: float4 x -> 2x half2 -> uint2 store
#pragma unroll
        for (int i = 0; i < 8; ++i) {
            const int idx = i * 512 + tid;
            const int r = idx >> 5, c4 = (idx & 31) * 4;
            const int row = row0 + r;
            float4 v = make_float4(0.f, 0.f, 0.f, 0.f);
            if (row < NN) v = *(const float4*)&x[row * FF + c4];
            __half2 lo = __floats2half2_rn(v.x, v.y);
            __half2 hi = __floats2half2_rn(v.z, v.w);
            *(uint2*)&As[r * STR + c4] = make_uint2(*(uint32_t*)&lo, *(uint32_t*)&hi);
        }
    }
    __syncthreads();

    const int warp = tid >> 5, lane = tid & 31;
    const int wr = warp >> 2, wc = warp & 3;
    const int mb = wr * 32, nb = wc * 32;
    const int g = lane >> 2, t = lane & 3, q = lane >> 3;

    const unsigned As32 = smem_u32(As);
    const unsigned Bs32 = smem_u32(Bs);
    unsigned aaddr[2], baddr[2];
#pragma unroll
    for (int mt = 0; mt < 2; ++mt)
        aaddr[mt] = As32 + ((mb + mt * 16 + (lane & 15)) * STR + (lane >> 4) * 8) * 2;
    const int brow_l = (lane & 7) + (q >> 1) * 8;
    const int bcol_l = (q & 1) * 8;

    float acc[2][4][4];
#pragma unroll
    for (int h = 0; h < 2; ++h) {
#pragma unroll
        for (int p = 0; p < 2; ++p)
            baddr[p] = Bs32 + ((h * 128 + nb + p * 16 + brow_l) * STR + bcol_l) * 2;
#pragma unroll
        for (int mt = 0; mt < 2; ++mt)
#pragma unroll
            for (int nt = 0; nt < 4; ++nt)
#pragma unroll
                for (int c = 0; c < 4; ++c) acc[mt][nt][c] = 0.f;

        GEMM_BODY(aaddr, baddr, acc)

#pragma unroll
        for (int mt = 0; mt < 2; ++mt) {
            const int rl = mb + mt * 16 + g;
            const int rA = row0 + rl;
#pragma unroll
            for (int nt = 0; nt < 4; ++nt) {
                const int col = nb + nt * 8 + 2 * t;
                if (h == 0) {
                    if (rA < NN)
                        *(float2*)&g_cproj[rA * FF + col] =
                            make_float2(acc[mt][nt][0], acc[mt][nt][1]);
                    if (rA + 8 < NN)
                        *(float2*)&g_cproj[(rA + 8) * FF + col] =
                            make_float2(acc[mt][nt][2], acc[mt][nt][3]);
                } else {
                    if (rA < NN) {
                        const uint32_t xa = *(uint32_t*)&As[rl * STR + col];
                        __half2 v0, v1;
                        v0.x = ((const __half2*)&xa)->x;
                        v0.y = __float2half_rn(acc[mt][nt][0]);
                        v1.x = ((const __half2*)&xa)->y;
                        v1.y = __float2half_rn(acc[mt][nt][1]);
                        *(uint2*)&g_xn2[rA * FF + col] =
                            make_uint2(*(uint32_t*)&v0, *(uint32_t*)&v1);
                    }
                    if (rA + 8 < NN) {
                        const uint32_t xa = *(uint32_t*)&As[(rl + 8) * STR + col];
                        __half2 v2, v3;
                        v2.x = ((const __half2*)&xa)->x;
                        v2.y = __float2half_rn(acc[mt][nt][2]);
                        v3.x = ((const __half2*)&xa)->y;
                        v3.y = __float2half_rn(acc[mt][nt][3]);
                        *(uint2*)&g_xn2[(rA + 8) * FF + col] =
                            make_uint2(*(uint32_t*)&v2, *(uint32_t*)&v3);
                    }
                }
            }
        }
    }
}

// ============================================================================
// K2: edge gather (uint4 16B loads: 4 col-pairs/thread) -> x_new fp16 into As,
// then support = x_new @ W.  512 threads = 32 col-quads x 16 row-groups(8 rows).
// ============================================================================
__global__ __launch_bounds__(512, 2) void k_agg_support(const float* __restrict__ x,
                                                        const int* __restrict__ esrc) {
    extern __shared__ __half sm[];
    __half* As = sm;
    __half* Bs = sm + 128 * STR;
    const int tid = threadIdx.x;
    const int row0 = blockIdx.x * 128;

    {   // B: prepped W^T tile (2176 uint4)
        uint4* dst = (uint4*)Bs;
        const uint4* src = (const uint4*)(g_B + 2 * MATH);
#pragma unroll
        for (int i = 0; i < 5; ++i) {
            const int idx = i * 512 + tid;
            if (idx < 2176) dst[idx] = src[idx];
        }
    }

    // Gather: thread = (col-quad c4 = lane, row-group rg); 8 rows per thread.
    const int c4 = tid & 31, rg = tid >> 5;
#pragma unroll 2
    for (int i = 0; i < 8; ++i) {
        const int r = rg * 8 + i;
        const int n = row0 + r;
        float4 v = make_float4(0.f, 0.f, 0.f, 0.f);
        if (n < NN) {
            const float4 cp0 = *(const float4*)&g_cproj[n * FF + 4 * c4];
            const int* es = esrc + n * DEG;
            float a0 = 0.f, a1 = 0.f, a2 = 0.f, a3 = 0.f;
#pragma unroll
            for (int e = 0; e < DEG; ++e) {
                const int s = es[e];                          // uniform per warp
                const uint4 u = *(const uint4*)&g_xn2[s * FF + 4 * c4];  // 16B gather
                const float2 f0 = __half22float2(*(const __half2*)&u.x);
                const float2 f1 = __half22float2(*(const __half2*)&u.y);
                const float2 f2 = __half22float2(*(const __half2*)&u.z);
                const float2 f3 = __half22float2(*(const __half2*)&u.w);
                a0 = fmaf(fmaf(0.5f, tanh_approx(0.5f * (cp0.x + f0.y)), 0.5f), f0.x, a0);
                a1 = fmaf(fmaf(0.5f, tanh_approx(0.5f * (cp0.y + f1.y)), 0.5f), f1.x, a1);
                a2 = fmaf(fmaf(0.5f, tanh_approx(0.5f * (cp0.z + f2.y)), 0.5f), f2.x, a2);
                a3 = fmaf(fmaf(0.5f, tanh_approx(0.5f * (cp0.w + f3.y)), 0.5f), f3.x, a3);
            }
            const float4 xv = *(const float4*)&x[n * FF + 4 * c4];
            v = make_float4(xv.x + a0, xv.y + a1, xv.z + a2, xv.w + a3);
        }
        const __half2 h0 = __floats2half2_rn(v.x, v.y);
        const __half2 h1 = __floats2half2_rn(v.z, v.w);
        *(uint2*)&As[r * STR + 4 * c4] =
            make_uint2(*(const uint32_t*)&h0, *(const uint32_t*)&h1);
    }
    __syncthreads();

    const int warp = tid >> 5, lane = tid & 31;
    const int wr = warp >> 2, wc = warp & 3;
    const int mb = wr * 32, nb = wc * 32;
    const int g = lane >> 2, t = lane & 3, q = lane >> 3;

    const unsigned As32 = smem_u32(As);
    const unsigned Bs32 = smem_u32(Bs);
    unsigned aaddr[2], baddr[2];
#pragma unroll
    for (int mt = 0; mt < 2; ++mt)
        aaddr[mt] = As32 + ((mb + mt * 16 + (lane & 15)) * STR + (lane >> 4) * 8) * 2;
#pragma unroll
    for (int p = 0; p < 2; ++p)
        baddr[p] = Bs32 +
                   ((nb + p * 16 + (lane & 7) + (q >> 1) * 8) * STR + (q & 1) * 8) * 2;

    float acc[2][4][4];
#pragma unroll
    for (int mt = 0; mt < 2; ++mt)
#pragma unroll
        for (int nt = 0; nt < 4; ++nt)
#pragma unroll
            for (int c = 0; c < 4; ++c) acc[mt][nt][c] = 0.f;

    GEMM_BODY(aaddr, baddr, acc)

#pragma unroll
    for (int mt = 0; mt < 2; ++mt) {
        const int rA = row0 + mb + mt * 16 + g;
#pragma unroll
        for (int nt = 0; nt < 4; ++nt) {
            const int col = nb + nt * 8 + 2 * t;
            if (rA < NN)
                *(__half2*)&g_sup[rA * FF + col] =
                    __floats2half2_rn(acc[mt][nt][0], acc[mt][nt][1]);
            if (rA + 8 < NN)
                *(__half2*)&g_sup[(rA + 8) * FF + col] =
                    __floats2half2_rn(acc[mt][nt][2], acc[mt][nt][3]);
        }
    }
}

// ============================================================================
// K3: out[n] = bias + sum_e adj[e]*support[src].  uint4 (16B = 8 cols) gathers.
// 256 threads = 16 col-octets x 16 rows; 16 rows/block.
// ============================================================================
__global__ __launch_bounds__(256) void k_out(const float* __restrict__ adj,
                                             const int* __restrict__ esrc,
                                             const float* __restrict__ bias,
                                             float* __restrict__ out) {
    const int tid = threadIdx.x;
    const int c8 = tid & 15, r = tid >> 4;
    const int n = blockIdx.x * R3 + r;
    const float4 b0 = *(const float4*)&bias[8 * c8];
    const float4 b1 = *(const float4*)&bias[8 * c8 + 4];

    const int* es = esrc + n * DEG;
    const float* av = adj + n * DEG;
    float4 o0 = b0, o1 = b1;
#pragma unroll
    for (int e = 0; e < DEG; ++e) {
        const int s = es[e];
        const float a = av[e];
        const uint4 u = *(const uint4*)&g_sup[s * FF + 8 * c8];   // 16B gather
        const float2 f0 = __half22float2(*(const __half2*)&u.x);
        const float2 f1 = __half22float2(*(const __half2*)&u.y);
        const float2 f2 = __half22float2(*(const __half2*)&u.z);
        const float2 f3 = __half22float2(*(const __half2*)&u.w);
        o0.x = fmaf(a, f0.x, o0.x); o0.y = fmaf(a, f0.y, o0.y);
        o0.z = fmaf(a, f1.x, o0.z); o0.w = fmaf(a, f1.y, o0.w);
        o1.x = fmaf(a, f2.x, o1.x); o1.y = fmaf(a, f2.y, o1.y);
        o1.z = fmaf(a, f3.x, o1.z); o1.w = fmaf(a, f3.y, o1.w);
    }
    *(float4*)&out[n * FF + 8 * c8] = o0;
    *(float4*)&out[n * FF + 8 * c8 + 4] = o1;
}

// ============================================================================
extern "C" void kernel_launch(void* const* d_in, const int* in_sizes, int n_in,
                              void* d_out, int out_size) {
    const float* x    = (const float*)d_in[0];  // [N,128]
    const float* w    = (const float*)d_in[1];  // [128,128]
    const float* bias = (const float*)d_in[2];  // [128]
    const float* wm   = (const float*)d_in[3];  // [256,128]
    const float* adj  = (const float*)d_in[4];  // [E]
    const int*   esrc = (const int*)d_in[5];    // [E]
    float* out = (float*)d_out;

    cudaFuncSetAttribute(k_proj_mma, cudaFuncAttributeMaxDynamicSharedMemorySize, SM1);
    cudaFuncSetAttribute(k_agg_support, cudaFuncAttributeMaxDynamicSharedMemorySize, SM2);

    k_prep<<<192, 256>>>(w, wm);
    k_proj_mma<<<NT, 512, SM1>>>(x);
    k_agg_support<<<NT, 512, SM2>>>(x, esrc);
    k_out<<<NN / R3, 256>>>(adj, esrc, bias, out);
}

// round 14
// speedup vs baseline: 2.8535x; 1.0255x over previous
#include <cuda_runtime.h>
#include <cuda_fp16.h>
#include <cstdint>

// gcnmask N=50000, DEG=16 (edge_dst = repeat(arange(N),16) structural), F=128.
// compute_103 PTX target: tcgen05 unavailable -> sm_80-baseline mma.sync.m16n8k16
// (fp16 in, fp32 acc), ldmatrix fragments, weights pre-transposed fp16 (k_prep).
// R14: g_cproj -> fp16 (cuts 25.6MB traffic), edge-index/adj loads batched as
// int4/float4 (4x fewer uniform LDGs in both gather loops).
//
//   cproj = x @ Wm[0:128], nproj = x @ Wm[128:256]
//   agg[n] = sum_e sigmoid(cproj[n]+nproj[src]) * x[src];  x_new = x + agg
//   support = x_new @ W;  out[n] = bias + sum_e adj[e]*support[src]

#define NN 50000
#define FF 128
#define DEG 16
#define NT 391            // ceil(50000/128)
#define STR 136           // smem row stride in halfs (272B) -> conflict-free frags
#define MATH (128 * STR)  // halfs per weight tile
#define SM1 ((128 + 256) * STR * 2)   // k_proj: A + both Wm halves
#define SM2 ((128 + 128) * STR * 2)   // k2:     A + W
#define R3 16

__device__ __align__(16) __half  g_cph[NN * FF];  // cproj fp16
__device__ __align__(16) __half2 g_xn2[NN * FF];  // {x, nproj} — K2 gather stream
__device__ __align__(16) __half  g_sup[NN * FF];  // support fp16 — K3 gather stream
__device__ __align__(16) __half  g_B[3 * MATH];   // WmTop^T, WmBot^T, W^T  [n][k]

// ---- helpers ----
__device__ __forceinline__ float tanh_approx(float z) {
    float r; asm("tanh.approx.f32 %0, %1;" : "=f"(r) : "f"(z)); return r;
}
__device__ __forceinline__ unsigned smem_u32(const void* p) {
    unsigned r;
    asm("{ .reg .u64 t; cvta.to.shared.u64 t, %1; cvt.u32.u64 %0, t; }" : "=r"(r) : "l"(p));
    return r;
}
__device__ __forceinline__ void ldmat4(uint32_t& r0, uint32_t& r1, uint32_t& r2,
                                       uint32_t& r3, unsigned addr) {
    asm volatile("ldmatrix.sync.aligned.m8n8.x4.shared.b16 {%0,%1,%2,%3}, [%4];"
                 : "=r"(r0), "=r"(r1), "=r"(r2), "=r"(r3) : "r"(addr));
}
__device__ __forceinline__ void mma16816(float& d0, float& d1, float& d2, float& d3,
                                         uint32_t a0, uint32_t a1, uint32_t a2, uint32_t a3,
                                         uint32_t b0, uint32_t b1) {
    asm volatile(
        "mma.sync.aligned.m16n8k16.row.col.f32.f16.f16.f32 "
        "{%0,%1,%2,%3}, {%4,%5,%6,%7}, {%8,%9}, {%0,%1,%2,%3};"
        : "+f"(d0), "+f"(d1), "+f"(d2), "+f"(d3)
        : "r"(a0), "r"(a1), "r"(a2), "r"(a3), "r"(b0), "r"(b1));
}

// 16 warps, warp tile 32(M) x 32(N), K=128. As[r][k], Bs[n][k], stride STR.
#define GEMM_BODY(AADDR, BADDR, ACC)                                           \
    _Pragma("unroll")                                                          \
    for (int ks = 0; ks < 8; ++ks) {                                           \
        const int kb = ks * 32;                                                \
        uint32_t af[2][4];                                                     \
        ldmat4(af[0][0], af[0][1], af[0][2], af[0][3], (AADDR)[0] + kb);       \
        ldmat4(af[1][0], af[1][1], af[1][2], af[1][3], (AADDR)[1] + kb);       \
        _Pragma("unroll")                                                      \
        for (int p = 0; p < 2; ++p) {                                          \
            uint32_t b00, b01, b10, b11;                                       \
            ldmat4(b00, b01, b10, b11, (BADDR)[p] + kb);                       \
            _Pragma("unroll")                                                  \
            for (int mt = 0; mt < 2; ++mt) {                                   \
                mma16816(ACC[mt][2 * p][0], ACC[mt][2 * p][1],                 \
                         ACC[mt][2 * p][2], ACC[mt][2 * p][3],                 \
                         af[mt][0], af[mt][1], af[mt][2], af[mt][3], b00, b01);\
                mma16816(ACC[mt][2 * p + 1][0], ACC[mt][2 * p + 1][1],         \
                         ACC[mt][2 * p + 1][2], ACC[mt][2 * p + 1][3],         \
                         af[mt][0], af[mt][1], af[mt][2], af[mt][3], b10, b11);\
            }                                                                  \
        }                                                                      \
    }

// ============================================================================
// K0: one-time weight transpose to fp16 [n][k] stride-STR tiles.
// ============================================================================
__global__ __launch_bounds__(256) void k_prep(const float* __restrict__ w,
                                              const float* __restrict__ wm) {
    const int idx = blockIdx.x * 256 + threadIdx.x;   // 192 blocks = 49152
    const int m = idx >> 14, r = idx & 16383;
    const int k = r >> 7, n = r & 127;
    float v;
    if (m == 0)      v = __ldg(&wm[k * FF + n]);
    else if (m == 1) v = __ldg(&wm[(FF + k) * FF + n]);
    else             v = __ldg(&w[k * FF + n]);
    g_B[m * MATH + n * STR + k] = __float2half_rn(v);
}

// ============================================================================
// K1: both Wm halves resident; A tile built once; GEMM h=0 -> cproj fp16,
// h=1 -> g_xn2 {x,nproj} fp16 (uint2 coalesced stores).
// ============================================================================
__global__ __launch_bounds__(512, 2) void k_proj_mma(const float* __restrict__ x) {
    extern __shared__ __half sm[];
    __half* As = sm;                 // [128][STR]
    __half* Bs = sm + 128 * STR;     // [256][STR]
    const int tid = threadIdx.x;
    const int row0 = blockIdx.x * 128;

    {   // B: both prepped Wm tiles (4352 uint4)
        uint4* dst = (uint4*)Bs;
        const uint4* src = (const uint4*)g_B;
#pragma unroll
        for (int i = 0; i < 9; ++i) {
            const int idx = i * 512 + tid;
            if (idx < 4352) dst[idx] = src[idx];
        }
    }
    {   // A: float4 x -> 2x half2 -> uint2 store
#pragma unroll
        for (int i = 0; i < 8; ++i) {
            const int idx = i * 512 + tid;
            const int r = idx >> 5, c4 = (idx & 31) * 4;
            const int row = row0 + r;
            float4 v = make_float4(0.f, 0.f, 0.f, 0.f);
            if (row < NN) v = *(const float4*)&x[row * FF + c4];
            __half2 lo = __floats2half2_rn(v.x, v.y);
            __half2 hi = __floats2half2_rn(v.z, v.w);
            *(uint2*)&As[r * STR + c4] = make_uint2(*(uint32_t*)&lo, *(uint32_t*)&hi);
        }
    }
    __syncthreads();

    const int warp = tid >> 5, lane = tid & 31;
    const int wr = warp >> 2, wc = warp & 3;
    const int mb = wr * 32, nb = wc * 32;
    const int g = lane >> 2, t = lane & 3, q = lane >> 3;

    const unsigned As32 = smem_u32(As);
    const unsigned Bs32 = smem_u32(Bs);
    unsigned aaddr[2], baddr[2];
#pragma unroll
    for (int mt = 0; mt < 2; ++mt)
        aaddr[mt] = As32 + ((mb + mt * 16 + (lane & 15)) * STR + (lane >> 4) * 8) * 2;
    const int brow_l = (lane & 7) + (q >> 1) * 8;
    const int bcol_l = (q & 1) * 8;

    float acc[2][4][4];
#pragma unroll
    for (int h = 0; h < 2; ++h) {
#pragma unroll
        for (int p = 0; p < 2; ++p)
            baddr[p] = Bs32 + ((h * 128 + nb + p * 16 + brow_l) * STR + bcol_l) * 2;
#pragma unroll
        for (int mt = 0; mt < 2; ++mt)
#pragma unroll
            for (int nt = 0; nt < 4; ++nt)
#pragma unroll
                for (int c = 0; c < 4; ++c) acc[mt][nt][c] = 0.f;

        GEMM_BODY(aaddr, baddr, acc)

#pragma unroll
        for (int mt = 0; mt < 2; ++mt) {
            const int rl = mb + mt * 16 + g;
            const int rA = row0 + rl;
#pragma unroll
            for (int nt = 0; nt < 4; ++nt) {
                const int col = nb + nt * 8 + 2 * t;
                if (h == 0) {
                    if (rA < NN) {
                        const __half2 hv = __floats2half2_rn(acc[mt][nt][0], acc[mt][nt][1]);
                        *(uint32_t*)&g_cph[rA * FF + col] = *(const uint32_t*)&hv;
                    }
                    if (rA + 8 < NN) {
                        const __half2 hv = __floats2half2_rn(acc[mt][nt][2], acc[mt][nt][3]);
                        *(uint32_t*)&g_cph[(rA + 8) * FF + col] = *(const uint32_t*)&hv;
                    }
                } else {
                    if (rA < NN) {
                        const uint32_t xa = *(uint32_t*)&As[rl * STR + col];
                        __half2 v0, v1;
                        v0.x = ((const __half2*)&xa)->x;
                        v0.y = __float2half_rn(acc[mt][nt][0]);
                        v1.x = ((const __half2*)&xa)->y;
                        v1.y = __float2half_rn(acc[mt][nt][1]);
                        *(uint2*)&g_xn2[rA * FF + col] =
                            make_uint2(*(uint32_t*)&v0, *(uint32_t*)&v1);
                    }
                    if (rA + 8 < NN) {
                        const uint32_t xa = *(uint32_t*)&As[(rl + 8) * STR + col];
                        __half2 v2, v3;
                        v2.x = ((const __half2*)&xa)->x;
                        v2.y = __float2half_rn(acc[mt][nt][2]);
                        v3.x = ((const __half2*)&xa)->y;
                        v3.y = __float2half_rn(acc[mt][nt][3]);
                        *(uint2*)&g_xn2[(rA + 8) * FF + col] =
                            make_uint2(*(uint32_t*)&v2, *(uint32_t*)&v3);
                    }
                }
            }
        }
    }
}

// ============================================================================
// K2: edge gather (uint4 16B loads, batched int4 edge indices) -> x_new fp16
// into As, then support = x_new @ W.  512 thr = 32 col-quads x 16 row-groups.
// ============================================================================
__global__ __launch_bounds__(512, 2) void k_agg_support(const float* __restrict__ x,
                                                        const int* __restrict__ esrc) {
    extern __shared__ __half sm[];
    __half* As = sm;
    __half* Bs = sm + 128 * STR;
    const int tid = threadIdx.x;
    const int row0 = blockIdx.x * 128;

    {   // B: prepped W^T tile (2176 uint4)
        uint4* dst = (uint4*)Bs;
        const uint4* src = (const uint4*)(g_B + 2 * MATH);
#pragma unroll
        for (int i = 0; i < 5; ++i) {
            const int idx = i * 512 + tid;
            if (idx < 2176) dst[idx] = src[idx];
        }
    }

    // Gather: thread = (col-quad c4 = lane, row-group rg); 8 rows per thread.
    const int c4 = tid & 31, rg = tid >> 5;
#pragma unroll 2
    for (int i = 0; i < 8; ++i) {
        const int r = rg * 8 + i;
        const int n = row0 + r;
        float4 v = make_float4(0.f, 0.f, 0.f, 0.f);
        if (n < NN) {
            // cproj fp16: one uint2 (4 cols)
            const uint2 cpu = *(const uint2*)&g_cph[n * FF + 4 * c4];
            const float2 cpa = __half22float2(*(const __half2*)&cpu.x);
            const float2 cpb = __half22float2(*(const __half2*)&cpu.y);
            // edge indices: 4x int4 (uniform per warp)
            const int4* ep = (const int4*)(esrc + n * DEG);
            int sidx[16];
#pragma unroll
            for (int b = 0; b < 4; ++b) {
                const int4 e4 = __ldg(&ep[b]);
                sidx[4 * b] = e4.x; sidx[4 * b + 1] = e4.y;
                sidx[4 * b + 2] = e4.z; sidx[4 * b + 3] = e4.w;
            }
            float a0 = 0.f, a1 = 0.f, a2 = 0.f, a3 = 0.f;
#pragma unroll
            for (int e = 0; e < DEG; ++e) {
                const uint4 u = *(const uint4*)&g_xn2[sidx[e] * FF + 4 * c4];  // 16B
                const float2 f0 = __half22float2(*(const __half2*)&u.x);
                const float2 f1 = __half22float2(*(const __half2*)&u.y);
                const float2 f2 = __half22float2(*(const __half2*)&u.z);
                const float2 f3 = __half22float2(*(const __half2*)&u.w);
                a0 = fmaf(fmaf(0.5f, tanh_approx(0.5f * (cpa.x + f0.y)), 0.5f), f0.x, a0);
                a1 = fmaf(fmaf(0.5f, tanh_approx(0.5f * (cpa.y + f1.y)), 0.5f), f1.x, a1);
                a2 = fmaf(fmaf(0.5f, tanh_approx(0.5f * (cpb.x + f2.y)), 0.5f), f2.x, a2);
                a3 = fmaf(fmaf(0.5f, tanh_approx(0.5f * (cpb.y + f3.y)), 0.5f), f3.x, a3);
            }
            const float4 xv = *(const float4*)&x[n * FF + 4 * c4];
            v = make_float4(xv.x + a0, xv.y + a1, xv.z + a2, xv.w + a3);
        }
        const __half2 h0 = __floats2half2_rn(v.x, v.y);
        const __half2 h1 = __floats2half2_rn(v.z, v.w);
        *(uint2*)&As[r * STR + 4 * c4] =
            make_uint2(*(const uint32_t*)&h0, *(const uint32_t*)&h1);
    }
    __syncthreads();

    const int warp = tid >> 5, lane = tid & 31;
    const int wr = warp >> 2, wc = warp & 3;
    const int mb = wr * 32, nb = wc * 32;
    const int g = lane >> 2, t = lane & 3, q = lane >> 3;

    const unsigned As32 = smem_u32(As);
    const unsigned Bs32 = smem_u32(Bs);
    unsigned aaddr[2], baddr[2];
#pragma unroll
    for (int mt = 0; mt < 2; ++mt)
        aaddr[mt] = As32 + ((mb + mt * 16 + (lane & 15)) * STR + (lane >> 4) * 8) * 2;
#pragma unroll
    for (int p = 0; p < 2; ++p)
        baddr[p] = Bs32 +
                   ((nb + p * 16 + (lane & 7) + (q >> 1) * 8) * STR + (q & 1) * 8) * 2;

    float acc[2][4][4];
#pragma unroll
    for (int mt = 0; mt < 2; ++mt)
#pragma unroll
        for (int nt = 0; nt < 4; ++nt)
#pragma unroll
            for (int c = 0; c < 4; ++c) acc[mt][nt][c] = 0.f;

    GEMM_BODY(aaddr, baddr, acc)

#pragma unroll
    for (int mt = 0; mt < 2; ++mt) {
        const int rA = row0 + mb + mt * 16 + g;
#pragma unroll
        for (int nt = 0; nt < 4; ++nt) {
            const int col = nb + nt * 8 + 2 * t;
            if (rA < NN)
                *(__half2*)&g_sup[rA * FF + col] =
                    __floats2half2_rn(acc[mt][nt][0], acc[mt][nt][1]);
            if (rA + 8 < NN)
                *(__half2*)&g_sup[(rA + 8) * FF + col] =
                    __floats2half2_rn(acc[mt][nt][2], acc[mt][nt][3]);
        }
    }
}

// ============================================================================
// K3: out[n] = bias + sum_e adj[e]*support[src].  uint4 gathers + batched
// int4/float4 index/adj loads.  256 threads = 16 col-octets x 16 rows.
// ============================================================================
__global__ __launch_bounds__(256) void k_out(const float* __restrict__ adj,
                                             const int* __restrict__ esrc,
                                             const float* __restrict__ bias,
                                             float* __restrict__ out) {
    const int tid = threadIdx.x;
    const int c8 = tid & 15, r = tid >> 4;
    const int n = blockIdx.x * R3 + r;
    const float4 b0 = *(const float4*)&bias[8 * c8];
    const float4 b1 = *(const float4*)&bias[8 * c8 + 4];

    // batched uniform loads: 4x int4 indices, 4x float4 adj
    const int4* ep = (const int4*)(esrc + n * DEG);
    const float4* ap = (const float4*)(adj + n * DEG);
    int sidx[16];
    float aw[16];
#pragma unroll
    for (int b = 0; b < 4; ++b) {
        const int4 e4 = __ldg(&ep[b]);
        const float4 a4 = __ldg(&ap[b]);
        sidx[4 * b] = e4.x; sidx[4 * b + 1] = e4.y;
        sidx[4 * b + 2] = e4.z; sidx[4 * b + 3] = e4.w;
        aw[4 * b] = a4.x; aw[4 * b + 1] = a4.y;
        aw[4 * b + 2] = a4.z; aw[4 * b + 3] = a4.w;
    }

    float4 o0 = b0, o1 = b1;
#pragma unroll
    for (int e = 0; e < DEG; ++e) {
        const float a = aw[e];
        const uint4 u = *(const uint4*)&g_sup[sidx[e] * FF + 8 * c8];   // 16B gather
        const float2 f0 = __half22float2(*(const __half2*)&u.x);
        const float2 f1 = __half22float2(*(const __half2*)&u.y);
        const float2 f2 = __half22float2(*(const __half2*)&u.z);
        const float2 f3 = __half22float2(*(const __half2*)&u.w);
        o0.x = fmaf(a, f0.x, o0.x); o0.y = fmaf(a, f0.y, o0.y);
        o0.z = fmaf(a, f1.x, o0.z); o0.w = fmaf(a, f1.y, o0.w);
        o1.x = fmaf(a, f2.x, o1.x); o1.y = fmaf(a, f2.y, o1.y);
        o1.z = fmaf(a, f3.x, o1.z); o1.w = fmaf(a, f3.y, o1.w);
    }
    *(float4*)&out[n * FF + 8 * c8] = o0;
    *(float4*)&out[n * FF + 8 * c8 + 4] = o1;
}

// ============================================================================
extern "C" void kernel_launch(void* const* d_in, const int* in_sizes, int n_in,
                              void* d_out, int out_size) {
    const float* x    = (const float*)d_in[0];  // [N,128]
    const float* w    = (const float*)d_in[1];  // [128,128]
    const float* bias = (const float*)d_in[2];  // [128]
    const float* wm   = (const float*)d_in[3];  // [256,128]
    const float* adj  = (const float*)d_in[4];  // [E]
    const int*   esrc = (const int*)d_in[5];    // [E]
    float* out = (float*)d_out;

    cudaFuncSetAttribute(k_proj_mma, cudaFuncAttributeMaxDynamicSharedMemorySize, SM1);
    cudaFuncSetAttribute(k_agg_support, cudaFuncAttributeMaxDynamicSharedMemorySize, SM2);

    k_prep<<<192, 256>>>(w, wm);
    k_proj_mma<<<NT, 512, SM1>>>(x);
    k_agg_support<<<NT, 512, SM2>>>(x, esrc);
    k_out<<<NN / R3, 256>>>(adj, esrc, bias, out);
}